// round 11
// baseline (speedup 1.0000x reference)
#include <cuda_runtime.h>
#include <cstdint>

// EntailmentConeLoss: loss = 0.5*( mean_i E(p_i,cpos_i) + mean_{i,k} relu(MARGIN - E(p_i,cneg_{ik})) )
// E(p,c) = relu(acos(clip(num/denom)) - asin(clip(BETA/(|p|+eps),0,1-eps)))
//
// Structure: R1's proven main kernel (one warp per pair, serial rows, diff-form
// energy, libm acos/asin, no register cap) + fused final reduction (st.global.cg
// partials, atom.acq_rel counter -- no threadfence, no CCTL.IVALL).
// New: warp reductions via redux.sync.add.s32 fixed-point (scale 2^20) instead of
// 5-stage shfl butterflies: 10 instr / 130cyc chain -> 5 instr / ~40cyc per sum.

#define C_CONST 100000
#define D_CONST 256
#define P_CONST 65536
#define K_CONST 4
#define BETA 0.1f
#define MARGIN 0.1f
#define EPS 1e-6f

#define WARPS_PER_BLOCK 8
#define THREADS_PER_BLOCK (WARPS_PER_BLOCK * 32)
#define NUM_BLOCKS (P_CONST / WARPS_PER_BLOCK)   // 8192

#define FXP_SCALE 1048576.0f          // 2^20
#define FXP_INV   (1.0f / 1048576.0f)

__device__ __align__(16) float g_partials[NUM_BLOCKS];
__device__ unsigned int g_count;   // zero-init; last block resets each call

__device__ __forceinline__ float warp_sum_shfl(float v) {
    #pragma unroll
    for (int o = 16; o > 0; o >>= 1) v += __shfl_xor_sync(0xFFFFFFFFu, v, o);
    return v;
}

// Warp-wide f32 sum via integer redux (sm_80+ HW op). Fixed-point 2^20:
// lane partials |v| < 60, warp sums |S| < 2048 -> no overflow; quantization
// error <= 32 * 2^-21 abs (~1e-7 rel on sums ~512). Deterministic.
__device__ __forceinline__ float warp_sum_redux(float v) {
    int i = __float2int_rn(v * FXP_SCALE);
    int s;
    asm("redux.sync.add.s32 %0, %1, 0xffffffff;" : "=r"(s) : "r"(i));
    return (float)s * FXP_INV;
}

// Reference-exact energy from sums (R1 math, proven at 44.5us / rel_err 1e-7)
__device__ __forceinline__ float energy_from_sums(float sp2, float sc2, float sd2, float norm_p) {
    float num   = sc2 - sp2 - sd2;
    float denom = 2.0f * norm_p * sqrtf(sd2) + EPS;
    float cosang = num / denom;
    cosang = fminf(fmaxf(cosang, -1.0f + EPS), 1.0f - EPS);
    float ang = acosf(cosang);
    float sa  = BETA / (norm_p + EPS);
    sa = fminf(fmaxf(sa, 0.0f), 1.0f - EPS);
    float aperture = asinf(sa);
    return fmaxf(ang - aperture, 0.0f);
}

__global__ __launch_bounds__(THREADS_PER_BLOCK)
void cone_loss_kernel(const float* __restrict__ protos,
                      const int*   __restrict__ pairs,
                      const int*   __restrict__ neg_c,
                      float*       __restrict__ out) {
    const int wid  = threadIdx.x >> 5;
    const int lane = threadIdx.x & 31;
    const int pair = blockIdx.x * WARPS_PER_BLOCK + wid;   // one warp per pair

    __shared__ float s_warp[WARPS_PER_BLOCK];

    // ---- indices ----
    const int2 pc   = __ldg(reinterpret_cast<const int2*>(pairs) + pair);
    const int4 nidx = __ldg(reinterpret_cast<const int4*>(neg_c) + pair);

    // ---- p row (256 floats): 2x float4 per lane ----
    const float4* pbase = reinterpret_cast<const float4*>(protos);
    const float4* prow  = pbase + (size_t)pc.x * (D_CONST / 4);
    const float4 pa = __ldg(&prow[lane]);
    const float4 pb = __ldg(&prow[lane + 32]);

    const float sp2 = warp_sum_redux(pa.x*pa.x + pa.y*pa.y + pa.z*pa.z + pa.w*pa.w
                                   + pb.x*pb.x + pb.y*pb.y + pb.z*pb.z + pb.w*pb.w);
    const float norm_p = sqrtf(sp2);

    // ---- serial per-row processing (R1 diff form) ----
    float e_pos = 0.0f, neg_sum = 0.0f;
    #pragma unroll
    for (int r = 0; r < 5; r++) {
        int cidx = (r == 0) ? pc.y : ((r == 1) ? nidx.x : (r == 2) ? nidx.y
                                     : (r == 3) ? nidx.z : nidx.w);
        const float4* crow = pbase + (size_t)cidx * (D_CONST / 4);
        float4 ca = __ldg(&crow[lane]);
        float4 cb = __ldg(&crow[lane + 32]);

        float sc2_part = ca.x*ca.x + ca.y*ca.y + ca.z*ca.z + ca.w*ca.w
                       + cb.x*cb.x + cb.y*cb.y + cb.z*cb.z + cb.w*cb.w;
        float dax = ca.x - pa.x, day = ca.y - pa.y, daz = ca.z - pa.z, daw = ca.w - pa.w;
        float dbx = cb.x - pb.x, dby = cb.y - pb.y, dbz = cb.z - pb.z, dbw = cb.w - pb.w;
        float sd2_part = dax*dax + day*day + daz*daz + daw*daw
                       + dbx*dbx + dby*dby + dbz*dbz + dbw*dbw;

        float sc2 = warp_sum_redux(sc2_part);
        float sd2 = warp_sum_redux(sd2_part);

        float e = energy_from_sums(sp2, sc2, sd2, norm_p);
        if (r == 0) e_pos = e;
        else        neg_sum += fmaxf(MARGIN - e, 0.0f);
    }

    if (lane == 0) {
        s_warp[wid] = 0.5f * (e_pos   * (1.0f / (float)P_CONST)
                            + neg_sum * (1.0f / ((float)P_CONST * (float)K_CONST)));
    }
    __syncthreads();

    // ---- per-block partial -> L2 via st.cg, release-acquire counter (no threadfence) ----
    __shared__ bool is_last;
    if (threadIdx.x == 0) {
        float bsum = 0.0f;
        #pragma unroll
        for (int w = 0; w < WARPS_PER_BLOCK; w++) bsum += s_warp[w];
        asm volatile("st.global.cg.f32 [%0], %1;"
                     :: "l"(&g_partials[blockIdx.x]), "f"(bsum) : "memory");
        unsigned int old;
        asm volatile("atom.acq_rel.gpu.global.add.u32 %0, [%1], %2;"
                     : "=r"(old) : "l"(&g_count), "r"(1u) : "memory");
        is_last = (old == (unsigned int)(NUM_BLOCKS - 1));
    }
    __syncthreads();

    // ---- last block: reduce 8192 partials from L2 ----
    if (is_last) {
        const float4* src = reinterpret_cast<const float4*>(g_partials);
        float r = 0.0f;
        #pragma unroll
        for (int j = 0; j < 8; j++) {   // 2048 float4 = 256 thr * 8
            float4 v = __ldcg(&src[threadIdx.x + j * THREADS_PER_BLOCK]);
            r += (v.x + v.y) + (v.z + v.w);
        }
        r = warp_sum_shfl(r);
        if (lane == 0) s_warp[wid] = r;
        __syncthreads();
        if (threadIdx.x == 0) {
            float tot = 0.0f;
            #pragma unroll
            for (int w = 0; w < WARPS_PER_BLOCK; w++) tot += s_warp[w];
            out[0] = tot;
            atomicExch(&g_count, 0u);   // reset for next graph replay
        }
    }
}

extern "C" void kernel_launch(void* const* d_in, const int* in_sizes, int n_in,
                              void* d_out, int out_size) {
    const float* protos = (const float*)d_in[0];
    const int*   pairs  = (const int*)d_in[1];
    const int*   negc   = (const int*)d_in[2];
    float* out = (float*)d_out;

    cone_loss_kernel<<<NUM_BLOCKS, THREADS_PER_BLOCK>>>(protos, pairs, negc, out);
}